// round 15
// baseline (speedup 1.0000x reference)
#include <cuda_runtime.h>
#include <cstdint>

// Problem constants (match reference)
#define NN      100000
#define EE      3200000
#define GAMMA   0.1f

#define EDGE_THREADS (EE / 2)                   // 1,600,000 (2 edges each)
#define DAMP_THREADS ((NN + 1) / 2)             // 50,000 (2 nodes each)
#define TOTAL_THREADS (EDGE_THREADS + DAMP_THREADS)

__device__ __forceinline__ void red_add_v2(float* addr, float a, float b) {
    asm volatile("red.global.add.v2.f32 [%0], {%1, %2};"
                 :: "l"(addr), "f"(a), "f"(b) : "memory");
}

__device__ __forceinline__ int2 ldcs_int2(const int2* p) {
    int2 r;
    asm volatile("ld.global.cs.v2.s32 {%0,%1}, [%2];"
                 : "=r"(r.x), "=r"(r.y) : "l"(p));
    return r;
}

// FINAL locked configuration (best measured: 37.31 us total, 35.84 us kernel):
// Flat one-chunk-per-thread kernel over zero-initialized out:
//   threads [0, EDGE_THREADS):  2 edges each -> red.add message into out[dst]
//   threads [EDGE_THREADS, +DAMP_THREADS): 2 nodes -> red.add(-gamma*v)
// All contributions are atomic adds; no ordering needed.
// Rationale:
//  - binding resource is L1tex/LTS wavefront count (9.75M random-address ops);
//    measured kernel time sits at the model floor: ~33us ideal x 1.10 spread.
//  - 2 edges/thread is the measured-optimal burst depth
//    (16/8/4/2/1 edges/thread -> 38.2/37.7/36.9/36.4/37.1 us kernel time).
//  - memset graph node + single fused kernel has the lowest measured
//    non-kernel overhead of all structures tried.
__global__ void __launch_bounds__(256) fused_edge_damp_kernel(
        const float* __restrict__ x,
        const float* __restrict__ v,
        const int*   __restrict__ src,
        const int*   __restrict__ dst,
        float* __restrict__ out) {
    int t = blockIdx.x * blockDim.x + threadIdx.x;

    if (t < EDGE_THREADS) {
        const float2* __restrict__ x2 = reinterpret_cast<const float2*>(x);

        int2 s2  = ldcs_int2(reinterpret_cast<const int2*>(src) + t);
        int2 d2i = ldcs_int2(reinterpret_cast<const int2*>(dst) + t);

        int ss[2] = {s2.x, s2.y};
        int dd[2] = {d2i.x, d2i.y};

        float2 xs[2], xd[2];
#pragma unroll
        for (int k = 0; k < 2; k++) {
            xs[k] = __ldg(&x2[ss[k]]);
            xd[k] = __ldg(&x2[dd[k]]);
        }

#pragma unroll
        for (int k = 0; k < 2; k++) {
            float drx = xd[k].x - xs[k].x;
            float dry = xd[k].y - xs[k].y;
            float d2  = fmaf(drx, drx, dry * dry);
            // f = -C*P*(ab - R_C)/ab = 2*rsqrt(d2) - 2 ; zero for d2==0
            float f = (d2 > 0.0f) ? fmaf(2.0f, rsqrtf(d2), -2.0f) : 0.0f;
            red_add_v2(out + 2 * dd[k], f * drx, f * dry);
        }
    } else {
        int i2 = (t - EDGE_THREADS) * 2;
#pragma unroll
        for (int k = 0; k < 2; k++) {
            int i = i2 + k;
            if (i < NN) {
                float2 vv = __ldg(&reinterpret_cast<const float2*>(v)[i]);
                red_add_v2(out + 2 * i, -GAMMA * vv.x, -GAMMA * vv.y);
            }
        }
    }
}

extern "C" void kernel_launch(void* const* d_in, const int* in_sizes, int n_in,
                              void* d_out, int out_size) {
    const float* x   = (const float*)d_in[0];
    const float* v   = (const float*)d_in[1];
    const int*   src = (const int*)d_in[2];
    const int*   dst = (const int*)d_in[3];
    float* out = (float*)d_out;

    // Zero the accumulator (graph-capturable memset node).
    cudaMemsetAsync(out, 0, (size_t)out_size * sizeof(float), 0);

    int threads = 256;
    int blocks = (TOTAL_THREADS + threads - 1) / threads;  // 6446
    fused_edge_damp_kernel<<<blocks, threads>>>(x, v, src, dst, out);
}

// round 16
// speedup vs baseline: 1.0477x; 1.0477x over previous
#include <cuda_runtime.h>
#include <cstdint>

// Problem constants (match reference)
#define NN      100000
#define EE      3200000
#define GAMMA   0.1f

#define EDGE_THREADS (EE / 2)                   // 1,600,000 (2 edges each)
#define DAMP_THREADS ((NN + 1) / 2)             // 50,000 (2 nodes each)
#define TOTAL_THREADS (EDGE_THREADS + DAMP_THREADS)

__device__ __forceinline__ void red_add_v2(float* addr, float a, float b) {
    asm volatile("red.global.add.v2.f32 [%0], {%1, %2};"
                 :: "l"(addr), "f"(a), "f"(b) : "memory");
}

__device__ __forceinline__ int2 ldcs_int2(const int2* p) {
    int2 r;
    asm volatile("ld.global.cs.v2.s32 {%0,%1}, [%2];"
                 : "=r"(r.x), "=r"(r.y) : "l"(p));
    return r;
}

// FINAL locked configuration (best measured: 37.31 us total, 35.84 us kernel):
// Flat one-chunk-per-thread kernel over zero-initialized out:
//   threads [0, EDGE_THREADS):  2 edges each -> red.add message into out[dst]
//   threads [EDGE_THREADS, +DAMP_THREADS): 2 nodes -> red.add(-gamma*v)
// All contributions are atomic adds; no ordering needed.
// Rationale:
//  - binding resource is L1tex/LTS wavefront count (9.75M random-address ops);
//    measured kernel time sits at the model floor: ~33us ideal x 1.10 spread.
//  - 2 edges/thread is the measured-optimal burst depth
//    (16/8/4/2/1 edges/thread -> 38.2/37.7/36.9/36.4/37.1 us kernel time).
//  - memset graph node + single fused kernel has the lowest measured
//    non-kernel overhead of all structures tried.
__global__ void __launch_bounds__(256) fused_edge_damp_kernel(
        const float* __restrict__ x,
        const float* __restrict__ v,
        const int*   __restrict__ src,
        const int*   __restrict__ dst,
        float* __restrict__ out) {
    int t = blockIdx.x * blockDim.x + threadIdx.x;

    if (t < EDGE_THREADS) {
        const float2* __restrict__ x2 = reinterpret_cast<const float2*>(x);

        int2 s2  = ldcs_int2(reinterpret_cast<const int2*>(src) + t);
        int2 d2i = ldcs_int2(reinterpret_cast<const int2*>(dst) + t);

        int ss[2] = {s2.x, s2.y};
        int dd[2] = {d2i.x, d2i.y};

        float2 xs[2], xd[2];
#pragma unroll
        for (int k = 0; k < 2; k++) {
            xs[k] = __ldg(&x2[ss[k]]);
            xd[k] = __ldg(&x2[dd[k]]);
        }

#pragma unroll
        for (int k = 0; k < 2; k++) {
            float drx = xd[k].x - xs[k].x;
            float dry = xd[k].y - xs[k].y;
            float d2  = fmaf(drx, drx, dry * dry);
            // f = -C*P*(ab - R_C)/ab = 2*rsqrt(d2) - 2 ; zero for d2==0
            float f = (d2 > 0.0f) ? fmaf(2.0f, rsqrtf(d2), -2.0f) : 0.0f;
            red_add_v2(out + 2 * dd[k], f * drx, f * dry);
        }
    } else {
        int i2 = (t - EDGE_THREADS) * 2;
#pragma unroll
        for (int k = 0; k < 2; k++) {
            int i = i2 + k;
            if (i < NN) {
                float2 vv = __ldg(&reinterpret_cast<const float2*>(v)[i]);
                red_add_v2(out + 2 * i, -GAMMA * vv.x, -GAMMA * vv.y);
            }
        }
    }
}

extern "C" void kernel_launch(void* const* d_in, const int* in_sizes, int n_in,
                              void* d_out, int out_size) {
    const float* x   = (const float*)d_in[0];
    const float* v   = (const float*)d_in[1];
    const int*   src = (const int*)d_in[2];
    const int*   dst = (const int*)d_in[3];
    float* out = (float*)d_out;

    // Zero the accumulator (graph-capturable memset node).
    cudaMemsetAsync(out, 0, (size_t)out_size * sizeof(float), 0);

    int threads = 256;
    int blocks = (TOTAL_THREADS + threads - 1) / threads;  // 6446
    fused_edge_damp_kernel<<<blocks, threads>>>(x, v, src, dst, out);
}

// round 17
// speedup vs baseline: 1.0548x; 1.0069x over previous
#include <cuda_runtime.h>
#include <cstdint>

// Problem constants (match reference)
#define NN      100000
#define EE      3200000
#define GAMMA   0.1f

#define EDGE_THREADS (EE / 2)                   // 1,600,000 (2 edges each)
#define DAMP_THREADS ((NN + 1) / 2)             // 50,000 (2 nodes each)
#define TOTAL_THREADS (EDGE_THREADS + DAMP_THREADS)

__device__ __forceinline__ void red_add_v2(float* addr, float a, float b) {
    asm volatile("red.global.add.v2.f32 [%0], {%1, %2};"
                 :: "l"(addr), "f"(a), "f"(b) : "memory");
}

__device__ __forceinline__ int2 ldcs_int2(const int2* p) {
    int2 r;
    asm volatile("ld.global.cs.v2.s32 {%0,%1}, [%2];"
                 : "=r"(r.x), "=r"(r.y) : "l"(p));
    return r;
}

// FINAL locked configuration
// (best measured: 37.31 us total; 35.46 us kernel this round):
// Flat one-chunk-per-thread kernel over zero-initialized out:
//   threads [0, EDGE_THREADS):  2 edges each -> red.add message into out[dst]
//   threads [EDGE_THREADS, +DAMP_THREADS): 2 nodes -> red.add(-gamma*v)
// All contributions are atomic adds; no ordering needed.
// Rationale:
//  - binding resource is L1tex/LTS wavefront count (9.75M random-address ops);
//    measured kernel time sits at the model floor: ~33us ideal x 1.10 spread.
//  - 2 edges/thread is the measured-optimal burst depth
//    (16/8/4/2/1 edges/thread -> 38.2/37.7/36.9/36.4/37.1 us kernel time).
//  - memset graph node + single fused kernel has the lowest measured
//    non-kernel overhead of all structures tried.
__global__ void __launch_bounds__(256) fused_edge_damp_kernel(
        const float* __restrict__ x,
        const float* __restrict__ v,
        const int*   __restrict__ src,
        const int*   __restrict__ dst,
        float* __restrict__ out) {
    int t = blockIdx.x * blockDim.x + threadIdx.x;

    if (t < EDGE_THREADS) {
        const float2* __restrict__ x2 = reinterpret_cast<const float2*>(x);

        int2 s2  = ldcs_int2(reinterpret_cast<const int2*>(src) + t);
        int2 d2i = ldcs_int2(reinterpret_cast<const int2*>(dst) + t);

        int ss[2] = {s2.x, s2.y};
        int dd[2] = {d2i.x, d2i.y};

        float2 xs[2], xd[2];
#pragma unroll
        for (int k = 0; k < 2; k++) {
            xs[k] = __ldg(&x2[ss[k]]);
            xd[k] = __ldg(&x2[dd[k]]);
        }

#pragma unroll
        for (int k = 0; k < 2; k++) {
            float drx = xd[k].x - xs[k].x;
            float dry = xd[k].y - xs[k].y;
            float d2  = fmaf(drx, drx, dry * dry);
            // f = -C*P*(ab - R_C)/ab = 2*rsqrt(d2) - 2 ; zero for d2==0
            float f = (d2 > 0.0f) ? fmaf(2.0f, rsqrtf(d2), -2.0f) : 0.0f;
            red_add_v2(out + 2 * dd[k], f * drx, f * dry);
        }
    } else {
        int i2 = (t - EDGE_THREADS) * 2;
#pragma unroll
        for (int k = 0; k < 2; k++) {
            int i = i2 + k;
            if (i < NN) {
                float2 vv = __ldg(&reinterpret_cast<const float2*>(v)[i]);
                red_add_v2(out + 2 * i, -GAMMA * vv.x, -GAMMA * vv.y);
            }
        }
    }
}

extern "C" void kernel_launch(void* const* d_in, const int* in_sizes, int n_in,
                              void* d_out, int out_size) {
    const float* x   = (const float*)d_in[0];
    const float* v   = (const float*)d_in[1];
    const int*   src = (const int*)d_in[2];
    const int*   dst = (const int*)d_in[3];
    float* out = (float*)d_out;

    // Zero the accumulator (graph-capturable memset node).
    cudaMemsetAsync(out, 0, (size_t)out_size * sizeof(float), 0);

    int threads = 256;
    int blocks = (TOTAL_THREADS + threads - 1) / threads;  // 6446
    fused_edge_damp_kernel<<<blocks, threads>>>(x, v, src, dst, out);
}